// round 6
// baseline (speedup 1.0000x reference)
#include <cuda_runtime.h>
#include <cuda_fp16.h>
#include <cuda_fp8.h>
#include <cstdint>

#define DINLINE __device__ __forceinline__

// ---------------- problem constants ----------------
constexpr int C_    = 32;
constexpr int SP    = 13824;              // 24^3 spatial positions per (b, t)
constexpr long XSTR = 884736;             // 96^3, per-channel stride in x/out
constexpr int MTILES = 432;               // 55296 / 128
constexpr int NTILES = 4;                 // 1024 / 256
constexpr int KCHUNKS = 16;               // 1024 / 64
constexpr int A_TILE  = 16384;            // f16: 128 rows x 128B
constexpr int A8_TILE = 8192;             // e4m3: 128 rows x 64B
constexpr int B_TILE  = 32768;            // f16: 256 rows x 128B
constexpr int B8_TILE = 16384;            // e4m3: 256 rows x 64B
constexpr int OFF_AF8 = A_TILE;                   // 16384
constexpr int OFF_BH  = OFF_AF8 + A8_TILE;        // 24576
constexpr int OFF_BL8 = OFF_BH + B_TILE;          // 57344
constexpr int STAGE_BYTES = OFF_BL8 + B8_TILE;    // 73728
constexpr int NSTAGE = 3;
constexpr int SMEM_DYN = NSTAGE * STAGE_BYTES;    // 221184
constexpr float SCL_A = 0.0078125f;   // 2^-7
constexpr float SCL_B = 128.0f;       // 2^7

// ---------------- scratch (static device globals; no allocation) ----------------
__device__ __align__(1024) __half  g_Xh[(size_t)MTILES * KCHUNKS * 8192];
__device__ __align__(1024) uint8_t g_Xf8[(size_t)MTILES * KCHUNKS * A8_TILE];
__device__ __align__(1024) __half  g_Wh[(size_t)NTILES * KCHUNKS * 16384];
__device__ __align__(1024) uint8_t g_Wl8[(size_t)NTILES * KCHUNKS * B8_TILE];

// ---------------- helpers ----------------
DINLINE uint32_t smem_u32(const void* p) {
    uint32_t a;
    asm("{ .reg .u64 t; cvta.to.shared.u64 t, %1; cvt.u32.u64 %0, t; }" : "=r"(a) : "l"(p));
    return a;
}
DINLINE uint32_t swz(uint32_t o)  { return o ^ ((o >> 3) & 0x70); }    // 128B rows
DINLINE uint32_t swz64(uint32_t o){ return o ^ ((o >> 2) & 0x30); }    // 64B rows (2-bit)

DINLINE void cp_async16(uint32_t dst, const void* src) {
    asm volatile("cp.async.cg.shared.global [%0], [%1], 16;" :: "r"(dst), "l"(src));
}
#define CP_COMMIT() asm volatile("cp.async.commit_group;" ::: "memory")
#define CP_WAIT1()  asm volatile("cp.async.wait_group 1;" ::: "memory")
#define CP_WAIT0()  asm volatile("cp.async.wait_group 0;" ::: "memory")

DINLINE void ldsm_x4(uint32_t r[4], uint32_t addr) {
    asm volatile("ldmatrix.sync.aligned.m8n8.x4.shared.b16 {%0,%1,%2,%3}, [%4];"
                 : "=r"(r[0]), "=r"(r[1]), "=r"(r[2]), "=r"(r[3]) : "r"(addr));
}
DINLINE void mma16816(float c[4], const uint32_t a[4], uint32_t b0, uint32_t b1) {
    asm volatile(
        "mma.sync.aligned.m16n8k16.row.col.f32.f16.f16.f32 "
        "{%0,%1,%2,%3}, {%4,%5,%6,%7}, {%8,%9}, {%0,%1,%2,%3};"
        : "+f"(c[0]), "+f"(c[1]), "+f"(c[2]), "+f"(c[3])
        : "r"(a[0]), "r"(a[1]), "r"(a[2]), "r"(a[3]), "r"(b0), "r"(b1));
}
DINLINE void mma16832q(float c[4], const uint32_t a[4], uint32_t b0, uint32_t b1) {
    asm volatile(
        "mma.sync.aligned.m16n8k32.row.col.f32.e4m3.e4m3.f32 "
        "{%0,%1,%2,%3}, {%4,%5,%6,%7}, {%8,%9}, {%0,%1,%2,%3};"
        : "+f"(c[0]), "+f"(c[1]), "+f"(c[2]), "+f"(c[3])
        : "r"(a[0]), "r"(a[1]), "r"(a[2]), "r"(a[3]), "r"(b0), "r"(b1));
}

// ---------------- prepass: x -> rolled f16 + e4m3(x*2^-7) tiles ----------------
__global__ void __launch_bounds__(128) prepass_x(const float* __restrict__ x) {
    __shared__ __align__(16) __half  shh[8192];
    __shared__ __align__(16) uint8_t shf[A8_TILE];
    const int bx  = blockIdx.x;          // = mt*16 + kc
    const int mt  = bx >> 4;
    const int kc  = bx & 15;
    const int tid = threadIdx.x;
    const int bg  = mt / 108;
    const int b   = bg >> 1;
    const int g   = bg & 1;
    const int sp0 = (mt % 108) * 128;
    const float* xb = x + (size_t)b * C_ * XSTR + sp0 + tid;

    #pragma unroll 8
    for (int j = 0; j < 64; ++j) {
        const int k = kc * 64 + j;
        const int c = k & 31;
        const int s = k >> 5;
        const int t = (g * 32 + s + 48) & 63;
        const float v = xb[(size_t)c * XSTR + (size_t)t * SP];
        *(__half*)((char*)shh + swz((uint32_t)tid * 128 + (uint32_t)j * 2)) = __float2half_rn(v);
        shf[swz64((uint32_t)tid * 64 + (uint32_t)j)] =
            (uint8_t)__nv_cvt_float_to_fp8(v * SCL_A, __NV_SATFINITE, __NV_E4M3);
    }
    __syncthreads();
    const uint4* s4h = (const uint4*)shh;
    const uint4* s4f = (const uint4*)shf;
    uint4* dh = (uint4*)((char*)g_Xh + (size_t)bx * A_TILE);
    uint4* df = (uint4*)(g_Xf8 + (size_t)bx * A8_TILE);
    #pragma unroll
    for (int i = tid; i < 1024; i += 128) dh[i] = s4h[i];
    #pragma unroll
    for (int i = tid; i < 512; i += 128)  df[i] = s4f[i];
}

// ---------------- prepass: W -> f16 hi + e4m3(lo*2^7) tiles ----------------
__global__ void __launch_bounds__(128) prepass_w(const float* __restrict__ W) {
    const int bx  = blockIdx.x;          // = nt*16 + kc
    const int nt  = bx >> 4;
    const int kc  = bx & 15;
    const int tid = threadIdx.x;
    const int j   = tid & 63;
    char*    dh = (char*)g_Wh + (size_t)bx * B_TILE;
    uint8_t* dl = g_Wl8 + (size_t)bx * B8_TILE;
    for (int r = (tid >> 6); r < 256; r += 2) {
        const int o = nt * 256 + r;
        const float v = W[(size_t)o * 1024 + kc * 64 + j];
        const __half hi = __float2half_rn(v);
        const float  lo = v - __half2float(hi);
        *(__half*)(dh + swz((uint32_t)r * 128 + (uint32_t)j * 2)) = hi;
        dl[swz64((uint32_t)r * 64 + (uint32_t)j)] =
            (uint8_t)__nv_cvt_float_to_fp8(lo * SCL_B, __NV_SATFINITE, __NV_E4M3);
    }
}

// ---------------- GEMM: f16 hh + fp8 hl, CTA 128x256, 3-stage pipeline ----------------
DINLINE void issue_loads(int kc, int s, int mt, int nt, int tid, uint32_t smem_base) {
    const char* aH = (const char*)g_Xh + (size_t)(mt * 16 + kc) * A_TILE;
    const char* aF = (const char*)g_Xf8 + (size_t)(mt * 16 + kc) * A8_TILE;
    const char* bH = (const char*)g_Wh + (size_t)(nt * 16 + kc) * B_TILE;
    const char* bL = (const char*)g_Wl8 + (size_t)(nt * 16 + kc) * B8_TILE;
    const uint32_t sb = smem_base + s * STAGE_BYTES;
    const uint32_t to = (uint32_t)tid * 16;
    #pragma unroll
    for (int i = 0; i < 2; ++i)
        cp_async16(sb + i * 8192 + to, aH + i * 8192 + to);
    cp_async16(sb + OFF_AF8 + to, aF + to);
    #pragma unroll
    for (int i = 0; i < 4; ++i)
        cp_async16(sb + OFF_BH + i * 8192 + to, bH + i * 8192 + to);
    #pragma unroll
    for (int i = 0; i < 2; ++i)
        cp_async16(sb + OFF_BL8 + i * 8192 + to, bL + i * 8192 + to);
}

__global__ void __launch_bounds__(512, 1) gemm_k(const float* __restrict__ bias,
                                                 float* __restrict__ out) {
    extern __shared__ __align__(1024) char smem[];
    const uint32_t smem_base = smem_u32(smem);
    const int tid = threadIdx.x;
    const int l   = tid & 31;
    const int wid = tid >> 5;
    const int wm  = wid & 3;     // m 32-block
    const int wn  = wid >> 2;    // n 64-block
    const int bx  = blockIdx.x;
    const int nt  = bx & 3;
    const int mt  = bx >> 2;

    // per-lane ldmatrix address components (f16 tiles, 128B rows)
    uint32_t a_off[2], a_ph[2];
    #pragma unroll
    for (int mb = 0; mb < 2; ++mb) {
        const int row = wm * 32 + mb * 16 + (l & 15);
        a_off[mb] = (uint32_t)row * 128;
        a_ph[mb]  = (uint32_t)(row & 7) * 16;
    }
    const uint32_t a_half = (uint32_t)(l >> 4) * 16;
    const int bmat = l >> 3;
    uint32_t b_off[4], b_ph[4];
    #pragma unroll
    for (int nb2 = 0; nb2 < 4; ++nb2) {
        const int row = wn * 64 + nb2 * 16 + (bmat >> 1) * 8 + (l & 7);
        b_off[nb2] = (uint32_t)row * 128;
        b_ph[nb2]  = (uint32_t)(row & 7) * 16;
    }
    const uint32_t b_half = (uint32_t)(bmat & 1) * 16;
    // fp8 tiles: 64B rows, row offsets = f16 offsets >> 1, phase = (l&3)*16
    const uint32_t ph8    = (uint32_t)(l & 3) * 16;
    const uint32_t a8half = a_half;               // (l>>4)*16 selects k-half bytes
    const uint32_t b8half = (uint32_t)(bmat & 1) * 16;

    float acc[2][8][4];
    #pragma unroll
    for (int mb = 0; mb < 2; ++mb)
        #pragma unroll
        for (int nb = 0; nb < 8; ++nb)
            #pragma unroll
            for (int i = 0; i < 4; ++i) acc[mb][nb][i] = 0.f;

    // prologue: stages 0,1
    issue_loads(0, 0, mt, nt, tid, smem_base); CP_COMMIT();
    issue_loads(1, 1, mt, nt, tid, smem_base); CP_COMMIT();

    int s = 0, s2 = 2;   // consume stage, prefetch stage
    for (int it = 0; it < KCHUNKS; ++it) {
        CP_WAIT1();
        __syncthreads();
        if (it + 2 < KCHUNKS) issue_loads(it + 2, s2, mt, nt, tid, smem_base);
        CP_COMMIT();

        const uint32_t sb  = smem_base + s * STAGE_BYTES;
        const uint32_t sAf = sb + OFF_AF8;
        const uint32_t sBh = sb + OFF_BH;
        const uint32_t sBl = sb + OFF_BL8;

        // ---- hh: f16 x f16 ----
        #pragma unroll
        for (int kk = 0; kk < 4; ++kk) {
            const uint32_t ka = (uint32_t)kk * 32 + a_half;
            const uint32_t kb = (uint32_t)kk * 32 + b_half;
            uint32_t ah[2][4], bf[8][2];
            #pragma unroll
            for (int mb = 0; mb < 2; ++mb)
                ldsm_x4(ah[mb], sb + a_off[mb] + (ka ^ a_ph[mb]));
            #pragma unroll
            for (int nb2 = 0; nb2 < 4; ++nb2) {
                uint32_t r[4];
                ldsm_x4(r, sBh + b_off[nb2] + (kb ^ b_ph[nb2]));
                bf[nb2 * 2][0]     = r[0]; bf[nb2 * 2][1]     = r[1];
                bf[nb2 * 2 + 1][0] = r[2]; bf[nb2 * 2 + 1][1] = r[3];
            }
            #pragma unroll
            for (int mb = 0; mb < 2; ++mb)
                #pragma unroll
                for (int nb = 0; nb < 8; ++nb)
                    mma16816(acc[mb][nb], ah[mb], bf[nb][0], bf[nb][1]);
        }

        // ---- hl: e4m3 x e4m3, k32 per inst (2 steps cover the 64-K chunk) ----
        #pragma unroll
        for (int j = 0; j < 2; ++j) {
            uint32_t af[2][4];
            #pragma unroll
            for (int mb = 0; mb < 2; ++mb)
                af_load: ldsm_x4(af[mb], sAf + (a_off[mb] >> 1)
                                 + (((uint32_t)j * 32 + a8half) ^ ph8));
            #pragma unroll
            for (int nb2 = 0; nb2 < 4; ++nb2) {
                uint32_t r[4];
                ldsm_x4(r, sBl + (b_off[nb2] >> 1)
                           + (((uint32_t)j * 32 + b8half) ^ ph8));
                #pragma unroll
                for (int mb = 0; mb < 2; ++mb) {
                    mma16832q(acc[mb][nb2 * 2],     af[mb], r[0], r[1]);
                    mma16832q(acc[mb][nb2 * 2 + 1], af[mb], r[2], r[3]);
                }
            }
        }

        s = (s == 2) ? 0 : s + 1;
        s2 = (s2 == 2) ? 0 : s2 + 1;
    }
    CP_WAIT0();
    __syncthreads();

    // ---------------- epilogue: transpose C via SMEM, coalesced scatter ----------------
    float* sC = (float*)smem;            // 128 rows x 34 floats (padded)
    const int bg = mt / 108;
    const int b  = bg >> 1;
    const int g  = bg & 1;
    const int sp0 = (mt % 108) * 128;

    const int col  = tid >> 4;           // 0..31
    const int rb   = (tid & 15) * 8;     // row base, 8 rows per thread
    float* outB = out + (size_t)b * C_ * XSTR + sp0;

    #pragma unroll
    for (int p = 0; p < 8; ++p) {        // 32-col passes over the 256-wide tile
        if (wn == (p >> 1)) {
            const int nbb = (p & 1) * 4;
            #pragma unroll
            for (int mb = 0; mb < 2; ++mb) {
                #pragma unroll
                for (int nbl = 0; nbl < 4; ++nbl) {
                    const int nb  = nbb + nbl;
                    const int row = wm * 32 + mb * 16 + (l >> 2);
                    const int cc  = nbl * 8 + (l & 3) * 2;
                    *(float2*)&sC[row * 34 + cc]       = *(float2*)&acc[mb][nb][0];
                    *(float2*)&sC[(row + 8) * 34 + cc] = *(float2*)&acc[mb][nb][2];
                }
            }
        }
        __syncthreads();
        {
            const int o  = nt * 256 + p * 32 + col;
            const int sv = o >> 5;
            const int c  = o & 31;
            const int tp = (g * 32 + sv + 48) & 63;
            const float bia = __ldg(&bias[o]);
            float v[8];
            #pragma unroll
            for (int i = 0; i < 8; ++i) v[i] = sC[(rb + i) * 34 + col] + bia;
            float* dst = outB + (size_t)c * XSTR + (size_t)tp * SP + rb;
            *(float4*)&dst[0] = *(float4*)&v[0];
            *(float4*)&dst[4] = *(float4*)&v[4];
        }
        __syncthreads();
    }
}

// ---------------- host ----------------
extern "C" void kernel_launch(void* const* d_in, const int* in_sizes, int n_in,
                              void* d_out, int out_size) {
    const float* x    = (const float*)d_in[0];
    const float* W    = (const float*)d_in[1];
    const float* bias = (const float*)d_in[2];
    float* out = (float*)d_out;

    cudaFuncSetAttribute(gemm_k, cudaFuncAttributeMaxDynamicSharedMemorySize, SMEM_DYN);

    prepass_x<<<MTILES * KCHUNKS, 128>>>(x);                 // 6912 blocks
    prepass_w<<<NTILES * KCHUNKS, 128>>>(W);                 // 64 blocks
    gemm_k<<<MTILES * NTILES, 512, SMEM_DYN>>>(bias, out);   // 1728 blocks
}

// round 7
// speedup vs baseline: 1.2875x; 1.2875x over previous
#include <cuda_runtime.h>
#include <cuda_fp16.h>
#include <cstdint>

#define DINLINE __device__ __forceinline__

// ---------------- problem constants ----------------
constexpr int C_    = 32;
constexpr int SP    = 13824;              // 24^3 spatial positions per (b, t)
constexpr long XSTR = 884736;             // 96^3, per-channel stride in x/out
constexpr int MTILES = 432;               // 55296 / 128
constexpr int NTILES = 8;                 // 1024 / 128
constexpr int KCHUNKS = 16;               // 1024 / 64
constexpr int A_TILE = 16384;             // 128 rows x 128B (64 fp16)
constexpr int B_TILE = 16384;             // 128 rows x 128B
constexpr int STAGE_BYTES = A_TILE + 2 * B_TILE;      // 49152: Ah,Bh,Bl
constexpr int NSTAGE = 2;
constexpr int SMEM_DYN = NSTAGE * STAGE_BYTES;        // 98304 -> 2 CTAs/SM

// ---------------- scratch (static device globals; no allocation) ----------------
__device__ __align__(1024) __half g_Xh[(size_t)MTILES * KCHUNKS * 8192];
__device__ __align__(1024) __half g_Wh[(size_t)NTILES * KCHUNKS * 8192];
__device__ __align__(1024) __half g_Wl[(size_t)NTILES * KCHUNKS * 8192];

// ---------------- helpers ----------------
DINLINE uint32_t smem_u32(const void* p) {
    uint32_t a;
    asm("{ .reg .u64 t; cvta.to.shared.u64 t, %1; cvt.u32.u64 %0, t; }" : "=r"(a) : "l"(p));
    return a;
}
DINLINE uint32_t swz(uint32_t o) { return o ^ ((o >> 3) & 0x70); }

DINLINE void cp_async16(uint32_t dst, const void* src) {
    asm volatile("cp.async.cg.shared.global [%0], [%1], 16;" :: "r"(dst), "l"(src));
}
#define CP_COMMIT() asm volatile("cp.async.commit_group;" ::: "memory")
#define CP_WAIT1()  asm volatile("cp.async.wait_group 1;" ::: "memory")
#define CP_WAIT0()  asm volatile("cp.async.wait_group 0;" ::: "memory")

DINLINE void ldsm_x4(uint32_t r[4], uint32_t addr) {
    asm volatile("ldmatrix.sync.aligned.m8n8.x4.shared.b16 {%0,%1,%2,%3}, [%4];"
                 : "=r"(r[0]), "=r"(r[1]), "=r"(r[2]), "=r"(r[3]) : "r"(addr));
}
DINLINE void mma16816(float c[4], const uint32_t a[4], uint32_t b0, uint32_t b1) {
    asm volatile(
        "mma.sync.aligned.m16n8k16.row.col.f32.f16.f16.f32 "
        "{%0,%1,%2,%3}, {%4,%5,%6,%7}, {%8,%9}, {%0,%1,%2,%3};"
        : "+f"(c[0]), "+f"(c[1]), "+f"(c[2]), "+f"(c[3])
        : "r"(a[0]), "r"(a[1]), "r"(a[2]), "r"(a[3]), "r"(b0), "r"(b1));
}

// ---------------- prepass: x -> rolled fp16, pre-swizzled A tiles ----------------
__global__ void __launch_bounds__(128) prepass_x(const float* __restrict__ x) {
    __shared__ __align__(16) __half shh[8192];
    const int bx  = blockIdx.x;          // = mt*16 + kc
    const int mt  = bx >> 4;
    const int kc  = bx & 15;
    const int tid = threadIdx.x;
    const int bg  = mt / 108;
    const int b   = bg >> 1;
    const int g   = bg & 1;
    const int sp0 = (mt % 108) * 128;
    const float* xb = x + (size_t)b * C_ * XSTR + sp0 + tid;

    #pragma unroll 8
    for (int j = 0; j < 64; ++j) {
        const int k = kc * 64 + j;
        const int c = k & 31;
        const int s = k >> 5;
        const int t = (g * 32 + s + 48) & 63;
        const float v = xb[(size_t)c * XSTR + (size_t)t * SP];
        const uint32_t off = swz((uint32_t)tid * 128 + (uint32_t)j * 2);
        *(__half*)((char*)shh + off) = __float2half_rn(v);
    }
    __syncthreads();
    const uint4* s4h = (const uint4*)shh;
    uint4* dh = (uint4*)((char*)g_Xh + (size_t)bx * A_TILE);
    #pragma unroll
    for (int i = tid; i < 1024; i += 128) { dh[i] = s4h[i]; }
}

// ---------------- prepass: W -> split fp16 hi/lo, pre-swizzled 128-row B tiles ----------------
__global__ void __launch_bounds__(128) prepass_w(const float* __restrict__ W) {
    const int bx  = blockIdx.x;          // = nt*16 + kc
    const int nt  = bx >> 4;
    const int kc  = bx & 15;
    const int tid = threadIdx.x;
    const int j   = tid & 63;
    char* dh = (char*)g_Wh + (size_t)bx * B_TILE;
    char* dl = (char*)g_Wl + (size_t)bx * B_TILE;
    for (int r = (tid >> 6); r < 128; r += 2) {
        const int o = nt * 128 + r;
        const float v = W[(size_t)o * 1024 + kc * 64 + j];
        const __half hi = __float2half_rn(v);
        const __half lo = __float2half_rn(v - __half2float(hi));
        const uint32_t off = swz((uint32_t)r * 128 + (uint32_t)j * 2);
        *(__half*)(dh + off) = hi;
        *(__half*)(dl + off) = lo;
    }
}

// ---------------- GEMM: mma.sync fp16, CTA 128x128, 8 warps, 2 CTAs/SM ----------------
DINLINE void issue_loads(int kc, int s, int mt, int nt, int tid, uint32_t smem_base) {
    const char* aH = (const char*)g_Xh + (size_t)(mt * 16 + kc) * A_TILE;
    const char* bH = (const char*)g_Wh + (size_t)(nt * 16 + kc) * B_TILE;
    const char* bL = (const char*)g_Wl + (size_t)(nt * 16 + kc) * B_TILE;
    const uint32_t sAh = smem_base + s * STAGE_BYTES;
    const uint32_t sBh = sAh + A_TILE;
    const uint32_t sBl = sBh + B_TILE;
    const uint32_t to = (uint32_t)tid * 16;
    #pragma unroll
    for (int i = 0; i < 4; ++i) {
        const uint32_t o = (uint32_t)i * 4096 + to;
        cp_async16(sAh + o, aH + o);
        cp_async16(sBh + o, bH + o);
        cp_async16(sBl + o, bL + o);
    }
}

__global__ void __launch_bounds__(256, 2) gemm_k(const float* __restrict__ bias,
                                                 float* __restrict__ out) {
    extern __shared__ __align__(1024) char smem[];
    const uint32_t smem_base = smem_u32(smem);
    const int tid = threadIdx.x;
    const int l   = tid & 31;
    const int wid = tid >> 5;
    const int wm  = wid & 3;     // m 32-block (0..3)
    const int wn  = wid >> 2;    // n 64-block (0..1)
    const int bx  = blockIdx.x;
    const int nt  = bx & 7;
    const int mt  = bx >> 3;

    // per-lane ldmatrix address components
    uint32_t a_off[2], a_ph[2];
    #pragma unroll
    for (int mb = 0; mb < 2; ++mb) {
        const int row = wm * 32 + mb * 16 + (l & 15);
        a_off[mb] = (uint32_t)row * 128;
        a_ph[mb]  = (uint32_t)(row & 7) * 16;
    }
    const uint32_t a_half = (uint32_t)(l >> 4) * 16;
    const int bmat = l >> 3;
    uint32_t b_off[4], b_ph[4];
    #pragma unroll
    for (int nb2 = 0; nb2 < 4; ++nb2) {
        const int row = wn * 64 + nb2 * 16 + (bmat >> 1) * 8 + (l & 7);
        b_off[nb2] = (uint32_t)row * 128;
        b_ph[nb2]  = (uint32_t)(row & 7) * 16;
    }
    const uint32_t b_half = (uint32_t)(bmat & 1) * 16;

    float acc[2][8][4];
    #pragma unroll
    for (int mb = 0; mb < 2; ++mb)
        #pragma unroll
        for (int nb = 0; nb < 8; ++nb)
            #pragma unroll
            for (int i = 0; i < 4; ++i) acc[mb][nb][i] = 0.f;

    // prologue: stages 0,1
    issue_loads(0, 0, mt, nt, tid, smem_base); CP_COMMIT();
    issue_loads(1, 1, mt, nt, tid, smem_base); CP_COMMIT();

    for (int it = 0; it < KCHUNKS; ++it) {
        const int s = it & 1;
        CP_WAIT1();
        __syncthreads();

        const uint32_t sAh = smem_base + s * STAGE_BYTES;
        const uint32_t sBh = sAh + A_TILE;
        const uint32_t sBl = sBh + B_TILE;

        #pragma unroll
        for (int kk = 0; kk < 4; ++kk) {
            const uint32_t ka = (uint32_t)kk * 32 + a_half;
            const uint32_t kb = (uint32_t)kk * 32 + b_half;
            uint32_t ah[2][4], bf[8][2];
            // A-hi fragments (shared by hh and hl products)
            #pragma unroll
            for (int mb = 0; mb < 2; ++mb)
                ldsm_x4(ah[mb], sAh + a_off[mb] + (ka ^ a_ph[mb]));
            // B-hi fragments
            #pragma unroll
            for (int nb2 = 0; nb2 < 4; ++nb2) {
                uint32_t r[4];
                ldsm_x4(r, sBh + b_off[nb2] + (kb ^ b_ph[nb2]));
                bf[nb2 * 2][0]     = r[0]; bf[nb2 * 2][1]     = r[1];
                bf[nb2 * 2 + 1][0] = r[2]; bf[nb2 * 2 + 1][1] = r[3];
            }
            // hh
            #pragma unroll
            for (int mb = 0; mb < 2; ++mb)
                #pragma unroll
                for (int nb = 0; nb < 8; ++nb)
                    mma16816(acc[mb][nb], ah[mb], bf[nb][0], bf[nb][1]);
            // B-lo fragments (reuse bf regs), hl (Ah x Bl)
            #pragma unroll
            for (int nb2 = 0; nb2 < 4; ++nb2) {
                uint32_t r[4];
                ldsm_x4(r, sBl + b_off[nb2] + (kb ^ b_ph[nb2]));
                bf[nb2 * 2][0]     = r[0]; bf[nb2 * 2][1]     = r[1];
                bf[nb2 * 2 + 1][0] = r[2]; bf[nb2 * 2 + 1][1] = r[3];
            }
            #pragma unroll
            for (int mb = 0; mb < 2; ++mb)
                #pragma unroll
                for (int nb = 0; nb < 8; ++nb)
                    mma16816(acc[mb][nb], ah[mb], bf[nb][0], bf[nb][1]);
        }

        __syncthreads();
        if (it + 2 < KCHUNKS) issue_loads(it + 2, s, mt, nt, tid, smem_base);
        CP_COMMIT();
    }
    CP_WAIT0();
    __syncthreads();

    // ---------------- epilogue: transpose C via SMEM, coalesced scatter ----------------
    float* sC = (float*)smem;            // 128 rows x 34 floats (padded)
    const int bg = mt / 108;
    const int b  = bg >> 1;
    const int g  = bg & 1;
    const int sp0 = (mt % 108) * 128;

    const int col  = tid >> 3;           // 0..31
    const int rb   = (tid & 7) * 16;     // row base, 16 rows per thread
    float* outB = out + (size_t)b * C_ * XSTR + sp0;

    #pragma unroll
    for (int p = 0; p < 4; ++p) {        // 32-col passes over the 128-wide tile
        if (wn == (p >> 1)) {
            const int nbb = (p & 1) * 4;
            #pragma unroll
            for (int mb = 0; mb < 2; ++mb) {
                #pragma unroll
                for (int nbl = 0; nbl < 4; ++nbl) {
                    const int nb  = nbb + nbl;
                    const int row = wm * 32 + mb * 16 + (l >> 2);
                    const int cc  = nbl * 8 + (l & 3) * 2;
                    *(float2*)&sC[row * 34 + cc]       = *(float2*)&acc[mb][nb][0];
                    *(float2*)&sC[(row + 8) * 34 + cc] = *(float2*)&acc[mb][nb][2];
                }
            }
        }
        __syncthreads();
        {
            const int o  = nt * 128 + p * 32 + col;
            const int sv = o >> 5;
            const int c  = o & 31;
            const int tp = (g * 32 + sv + 48) & 63;
            const float bia = __ldg(&bias[o]);
            float v[16];
            #pragma unroll
            for (int i = 0; i < 16; ++i) v[i] = sC[(rb + i) * 34 + col] + bia;
            float* dst = outB + (size_t)c * XSTR + (size_t)tp * SP + rb;
            #pragma unroll
            for (int q = 0; q < 4; ++q)
                *(float4*)&dst[q * 4] = *(float4*)&v[q * 4];
        }
        __syncthreads();
    }
}

// ---------------- host ----------------
extern "C" void kernel_launch(void* const* d_in, const int* in_sizes, int n_in,
                              void* d_out, int out_size) {
    const float* x    = (const float*)d_in[0];
    const float* W    = (const float*)d_in[1];
    const float* bias = (const float*)d_in[2];
    float* out = (float*)d_out;

    cudaFuncSetAttribute(gemm_k, cudaFuncAttributeMaxDynamicSharedMemorySize, SMEM_DYN);

    prepass_x<<<MTILES * KCHUNKS, 128>>>(x);                 // 6912 blocks
    prepass_w<<<NTILES * KCHUNKS, 128>>>(W);                 // 128 blocks
    gemm_k<<<MTILES * NTILES, 256, SMEM_DYN>>>(bias, out);   // 3456 blocks
}

// round 8
// speedup vs baseline: 1.8956x; 1.4723x over previous
#include <cuda_runtime.h>
#include <cuda_fp16.h>
#include <cstdint>

#define DINLINE __device__ __forceinline__

// ---------------- problem constants ----------------
constexpr int C_    = 32;
constexpr int SP    = 13824;              // 24^3 spatial positions per (b, t)
constexpr long XSTR = 884736;             // 96^3, per-channel stride in x/out
constexpr int MTILES = 432;               // 55296 / 128
constexpr int NTILES = 8;                 // 1024 / 128
constexpr int KCHUNKS = 16;               // 1024 / 64
constexpr int A_TILE = 16384;             // 128 rows x 128B (64 fp16)
constexpr int B_TILE = 16384;             // 128 rows x 128B
constexpr int STAGE_BYTES = A_TILE + B_TILE;          // 32768: Ah,Bh
constexpr int NSTAGE = 3;
constexpr int SMEM_DYN = NSTAGE * STAGE_BYTES;        // 98304 -> 2 CTAs/SM

// ---------------- scratch (static device globals; no allocation) ----------------
__device__ __align__(1024) __half g_Xh[(size_t)MTILES * KCHUNKS * 8192];
__device__ __align__(1024) __half g_Wh[(size_t)NTILES * KCHUNKS * 8192];

// ---------------- helpers ----------------
DINLINE uint32_t smem_u32(const void* p) {
    uint32_t a;
    asm("{ .reg .u64 t; cvta.to.shared.u64 t, %1; cvt.u32.u64 %0, t; }" : "=r"(a) : "l"(p));
    return a;
}
DINLINE uint32_t swz(uint32_t o) { return o ^ ((o >> 3) & 0x70); }

DINLINE void cp_async16(uint32_t dst, const void* src) {
    asm volatile("cp.async.cg.shared.global [%0], [%1], 16;" :: "r"(dst), "l"(src));
}
#define CP_COMMIT() asm volatile("cp.async.commit_group;" ::: "memory")
#define CP_WAIT1()  asm volatile("cp.async.wait_group 1;" ::: "memory")
#define CP_WAIT0()  asm volatile("cp.async.wait_group 0;" ::: "memory")

DINLINE void ldsm_x4(uint32_t r[4], uint32_t addr) {
    asm volatile("ldmatrix.sync.aligned.m8n8.x4.shared.b16 {%0,%1,%2,%3}, [%4];"
                 : "=r"(r[0]), "=r"(r[1]), "=r"(r[2]), "=r"(r[3]) : "r"(addr));
}
DINLINE void mma16816(float c[4], const uint32_t a[4], uint32_t b0, uint32_t b1) {
    asm volatile(
        "mma.sync.aligned.m16n8k16.row.col.f32.f16.f16.f32 "
        "{%0,%1,%2,%3}, {%4,%5,%6,%7}, {%8,%9}, {%0,%1,%2,%3};"
        : "+f"(c[0]), "+f"(c[1]), "+f"(c[2]), "+f"(c[3])
        : "r"(a[0]), "r"(a[1]), "r"(a[2]), "r"(a[3]), "r"(b0), "r"(b1));
}

// ---------------- prepass: x -> rolled fp16, pre-swizzled A tiles ----------------
__global__ void __launch_bounds__(128) prepass_x(const float* __restrict__ x) {
    __shared__ __align__(16) __half shh[8192];
    const int bx  = blockIdx.x;          // = mt*16 + kc
    const int mt  = bx >> 4;
    const int kc  = bx & 15;
    const int tid = threadIdx.x;
    const int bg  = mt / 108;
    const int b   = bg >> 1;
    const int g   = bg & 1;
    const int sp0 = (mt % 108) * 128;
    const float* xb = x + (size_t)b * C_ * XSTR + sp0 + tid;

    #pragma unroll 8
    for (int j = 0; j < 64; ++j) {
        const int k = kc * 64 + j;
        const int c = k & 31;
        const int s = k >> 5;
        const int t = (g * 32 + s + 48) & 63;
        const float v = xb[(size_t)c * XSTR + (size_t)t * SP];
        const uint32_t off = swz((uint32_t)tid * 128 + (uint32_t)j * 2);
        *(__half*)((char*)shh + off) = __float2half_rn(v);
    }
    __syncthreads();
    const uint4* s4h = (const uint4*)shh;
    uint4* dh = (uint4*)((char*)g_Xh + (size_t)bx * A_TILE);
    #pragma unroll
    for (int i = tid; i < 1024; i += 128) { dh[i] = s4h[i]; }
}

// ---------------- prepass: W -> fp16, pre-swizzled 128-row B tiles ----------------
__global__ void __launch_bounds__(128) prepass_w(const float* __restrict__ W) {
    const int bx  = blockIdx.x;          // = nt*16 + kc
    const int nt  = bx >> 4;
    const int kc  = bx & 15;
    const int tid = threadIdx.x;
    const int j   = tid & 63;
    char* dh = (char*)g_Wh + (size_t)bx * B_TILE;
    for (int r = (tid >> 6); r < 128; r += 2) {
        const int o = nt * 128 + r;
        const float v = W[(size_t)o * 1024 + kc * 64 + j];
        const uint32_t off = swz((uint32_t)r * 128 + (uint32_t)j * 2);
        *(__half*)(dh + off) = __float2half_rn(v);
    }
}

// ---------------- GEMM: mma.sync fp16 single pass, CTA 128x128, 2 CTAs/SM ----------------
DINLINE void issue_loads(int kc, int s, int mt, int nt, int tid, uint32_t smem_base) {
    const char* aH = (const char*)g_Xh + (size_t)(mt * 16 + kc) * A_TILE;
    const char* bH = (const char*)g_Wh + (size_t)(nt * 16 + kc) * B_TILE;
    const uint32_t sAh = smem_base + s * STAGE_BYTES;
    const uint32_t sBh = sAh + A_TILE;
    const uint32_t to = (uint32_t)tid * 16;
    #pragma unroll
    for (int i = 0; i < 4; ++i) {
        const uint32_t o = (uint32_t)i * 4096 + to;
        cp_async16(sAh + o, aH + o);
        cp_async16(sBh + o, bH + o);
    }
}

__global__ void __launch_bounds__(256, 2) gemm_k(const float* __restrict__ bias,
                                                 float* __restrict__ out) {
    extern __shared__ __align__(1024) char smem[];
    const uint32_t smem_base = smem_u32(smem);
    const int tid = threadIdx.x;
    const int l   = tid & 31;
    const int wid = tid >> 5;
    const int wm  = wid & 3;     // m 32-block (0..3)
    const int wn  = wid >> 2;    // n 64-block (0..1)
    const int bx  = blockIdx.x;
    const int nt  = bx & 7;
    const int mt  = bx >> 3;

    // per-lane ldmatrix address components
    uint32_t a_off[2], a_ph[2];
    #pragma unroll
    for (int mb = 0; mb < 2; ++mb) {
        const int row = wm * 32 + mb * 16 + (l & 15);
        a_off[mb] = (uint32_t)row * 128;
        a_ph[mb]  = (uint32_t)(row & 7) * 16;
    }
    const uint32_t a_half = (uint32_t)(l >> 4) * 16;
    const int bmat = l >> 3;
    uint32_t b_off[4], b_ph[4];
    #pragma unroll
    for (int nb2 = 0; nb2 < 4; ++nb2) {
        const int row = wn * 64 + nb2 * 16 + (bmat >> 1) * 8 + (l & 7);
        b_off[nb2] = (uint32_t)row * 128;
        b_ph[nb2]  = (uint32_t)(row & 7) * 16;
    }
    const uint32_t b_half = (uint32_t)(bmat & 1) * 16;

    float acc[2][8][4];
    #pragma unroll
    for (int mb = 0; mb < 2; ++mb)
        #pragma unroll
        for (int nb = 0; nb < 8; ++nb)
            #pragma unroll
            for (int i = 0; i < 4; ++i) acc[mb][nb][i] = 0.f;

    // prologue: stages 0,1
    issue_loads(0, 0, mt, nt, tid, smem_base); CP_COMMIT();
    issue_loads(1, 1, mt, nt, tid, smem_base); CP_COMMIT();

    int sc = 0, sp = 2;   // consume stage, prefetch stage
    for (int it = 0; it < KCHUNKS; ++it) {
        CP_WAIT1();
        __syncthreads();
        if (it + 2 < KCHUNKS) issue_loads(it + 2, sp, mt, nt, tid, smem_base);
        CP_COMMIT();

        const uint32_t sAh = smem_base + sc * STAGE_BYTES;
        const uint32_t sBh = sAh + A_TILE;

        #pragma unroll
        for (int kk = 0; kk < 4; ++kk) {
            const uint32_t ka = (uint32_t)kk * 32 + a_half;
            const uint32_t kb = (uint32_t)kk * 32 + b_half;
            uint32_t ah[2][4], bf[8][2];
            #pragma unroll
            for (int mb = 0; mb < 2; ++mb)
                ldsm_x4(ah[mb], sAh + a_off[mb] + (ka ^ a_ph[mb]));
            #pragma unroll
            for (int nb2 = 0; nb2 < 4; ++nb2) {
                uint32_t r[4];
                ldsm_x4(r, sBh + b_off[nb2] + (kb ^ b_ph[nb2]));
                bf[nb2 * 2][0]     = r[0]; bf[nb2 * 2][1]     = r[1];
                bf[nb2 * 2 + 1][0] = r[2]; bf[nb2 * 2 + 1][1] = r[3];
            }
            #pragma unroll
            for (int mb = 0; mb < 2; ++mb)
                #pragma unroll
                for (int nb = 0; nb < 8; ++nb)
                    mma16816(acc[mb][nb], ah[mb], bf[nb][0], bf[nb][1]);
        }

        sc = (sc == 2) ? 0 : sc + 1;
        sp = (sp == 2) ? 0 : sp + 1;
    }
    CP_WAIT0();
    __syncthreads();

    // ---------------- epilogue: transpose C via SMEM, coalesced scatter ----------------
    float* sC = (float*)smem;            // 128 rows x 34 floats (padded)
    const int bg = mt / 108;
    const int b  = bg >> 1;
    const int g  = bg & 1;
    const int sp0 = (mt % 108) * 128;

    const int col  = tid >> 3;           // 0..31
    const int rb   = (tid & 7) * 16;     // row base, 16 rows per thread
    float* outB = out + (size_t)b * C_ * XSTR + sp0;

    #pragma unroll
    for (int p = 0; p < 4; ++p) {        // 32-col passes over the 128-wide tile
        if (wn == (p >> 1)) {
            const int nbb = (p & 1) * 4;
            #pragma unroll
            for (int mb = 0; mb < 2; ++mb) {
                #pragma unroll
                for (int nbl = 0; nbl < 4; ++nbl) {
                    const int nb  = nbb + nbl;
                    const int row = wm * 32 + mb * 16 + (l >> 2);
                    const int cc  = nbl * 8 + (l & 3) * 2;
                    *(float2*)&sC[row * 34 + cc]       = *(float2*)&acc[mb][nb][0];
                    *(float2*)&sC[(row + 8) * 34 + cc] = *(float2*)&acc[mb][nb][2];
                }
            }
        }
        __syncthreads();
        {
            const int o  = nt * 128 + p * 32 + col;
            const int sv = o >> 5;
            const int c  = o & 31;
            const int tp = (g * 32 + sv + 48) & 63;
            const float bia = __ldg(&bias[o]);
            float v[16];
            #pragma unroll
            for (int i = 0; i < 16; ++i) v[i] = sC[(rb + i) * 34 + col] + bia;
            float* dst = outB + (size_t)c * XSTR + (size_t)tp * SP + rb;
            #pragma unroll
            for (int q = 0; q < 4; ++q)
                *(float4*)&dst[q * 4] = *(float4*)&v[q * 4];
        }
        __syncthreads();
    }
}

// ---------------- host ----------------
extern "C" void kernel_launch(void* const* d_in, const int* in_sizes, int n_in,
                              void* d_out, int out_size) {
    const float* x    = (const float*)d_in[0];
    const float* W    = (const float*)d_in[1];
    const float* bias = (const float*)d_in[2];
    float* out = (float*)d_out;

    cudaFuncSetAttribute(gemm_k, cudaFuncAttributeMaxDynamicSharedMemorySize, SMEM_DYN);

    prepass_x<<<MTILES * KCHUNKS, 128>>>(x);                 // 6912 blocks
    prepass_w<<<NTILES * KCHUNKS, 128>>>(W);                 // 128 blocks
    gemm_k<<<MTILES * NTILES, 256, SMEM_DYN>>>(bias, out);   // 3456 blocks
}

// round 9
// speedup vs baseline: 2.3352x; 1.2319x over previous
#include <cuda_runtime.h>
#include <cuda_fp16.h>
#include <cstdint>

#define DINLINE __device__ __forceinline__

// ---------------- problem constants ----------------
constexpr int C_    = 32;
constexpr int SP    = 13824;              // 24^3 spatial positions per (b, t)
constexpr long XSTR = 884736;             // 96^3, per-channel stride in x/out
constexpr int MTILES = 432;               // 55296 / 128
constexpr int NTILES = 8;                 // 1024 / 128
constexpr int KCHUNKS = 16;               // 1024 / 64
constexpr int A_TILE = 16384;             // 128 rows x 128B (64 fp16)
constexpr int B_TILE = 16384;             // 128 rows x 128B
constexpr int STAGE_BYTES = A_TILE + B_TILE;          // 32768
constexpr int NSTAGE = 3;
constexpr int SMEM_DYN = NSTAGE * STAGE_BYTES;        // 98304 -> 2 CTAs/SM
constexpr int PT = 132;                   // sCT pitch (floats): conflict-free

// ---------------- scratch (static device globals; no allocation) ----------------
__device__ __align__(1024) __half g_Xh[(size_t)MTILES * KCHUNKS * 8192];
__device__ __align__(1024) __half g_Wh[(size_t)NTILES * KCHUNKS * 8192];

// ---------------- helpers ----------------
DINLINE uint32_t smem_u32(const void* p) {
    uint32_t a;
    asm("{ .reg .u64 t; cvta.to.shared.u64 t, %1; cvt.u32.u64 %0, t; }" : "=r"(a) : "l"(p));
    return a;
}
DINLINE uint32_t swz(uint32_t o) { return o ^ ((o >> 3) & 0x70); }

DINLINE void cp_async16(uint32_t dst, const void* src) {
    asm volatile("cp.async.cg.shared.global [%0], [%1], 16;" :: "r"(dst), "l"(src));
}
#define CP_COMMIT() asm volatile("cp.async.commit_group;" ::: "memory")
#define CP_WAIT1()  asm volatile("cp.async.wait_group 1;" ::: "memory")
#define CP_WAIT0()  asm volatile("cp.async.wait_group 0;" ::: "memory")

DINLINE void ldsm_x4(uint32_t r[4], uint32_t addr) {
    asm volatile("ldmatrix.sync.aligned.m8n8.x4.shared.b16 {%0,%1,%2,%3}, [%4];"
                 : "=r"(r[0]), "=r"(r[1]), "=r"(r[2]), "=r"(r[3]) : "r"(addr));
}
DINLINE void mma16816(float c[4], const uint32_t a[4], uint32_t b0, uint32_t b1) {
    asm volatile(
        "mma.sync.aligned.m16n8k16.row.col.f32.f16.f16.f32 "
        "{%0,%1,%2,%3}, {%4,%5,%6,%7}, {%8,%9}, {%0,%1,%2,%3};"
        : "+f"(c[0]), "+f"(c[1]), "+f"(c[2]), "+f"(c[3])
        : "r"(a[0]), "r"(a[1]), "r"(a[2]), "r"(a[3]), "r"(b0), "r"(b1));
}

// ---------------- prepass: x -> rolled fp16, pre-swizzled A tiles ----------------
__global__ void __launch_bounds__(128) prepass_x(const float* __restrict__ x) {
    __shared__ __align__(16) __half shh[8192];
    const int bx  = blockIdx.x;          // = mt*16 + kc
    const int mt  = bx >> 4;
    const int kc  = bx & 15;
    const int tid = threadIdx.x;
    const int bg  = mt / 108;
    const int b   = bg >> 1;
    const int g   = bg & 1;
    const int sp0 = (mt % 108) * 128;
    const float* xb = x + (size_t)b * C_ * XSTR + sp0 + tid;

    #pragma unroll 8
    for (int j = 0; j < 64; ++j) {
        const int k = kc * 64 + j;
        const int c = k & 31;
        const int s = k >> 5;
        const int t = (g * 32 + s + 48) & 63;
        const float v = xb[(size_t)c * XSTR + (size_t)t * SP];
        const uint32_t off = swz((uint32_t)tid * 128 + (uint32_t)j * 2);
        *(__half*)((char*)shh + off) = __float2half_rn(v);
    }
    __syncthreads();
    const uint4* s4h = (const uint4*)shh;
    uint4* dh = (uint4*)((char*)g_Xh + (size_t)bx * A_TILE);
    #pragma unroll
    for (int i = tid; i < 1024; i += 128) { dh[i] = s4h[i]; }
}

// ---------------- prepass: W -> fp16, pre-swizzled 128-row B tiles ----------------
__global__ void __launch_bounds__(128) prepass_w(const float* __restrict__ W) {
    const int bx  = blockIdx.x;          // = nt*16 + kc
    const int nt  = bx >> 4;
    const int kc  = bx & 15;
    const int tid = threadIdx.x;
    const int j   = tid & 63;
    char* dh = (char*)g_Wh + (size_t)bx * B_TILE;
    for (int r = (tid >> 6); r < 128; r += 2) {
        const int o = nt * 128 + r;
        const float v = W[(size_t)o * 1024 + kc * 64 + j];
        const uint32_t off = swz((uint32_t)r * 128 + (uint32_t)j * 2);
        *(__half*)(dh + off) = __float2half_rn(v);
    }
}

// ---------------- GEMM: mma.sync fp16, CTA 128x128, 2 CTAs/SM, seamless pipeline ----------------
DINLINE void issue_loads(int kc, int s, int mt, int nt, int tid, uint32_t smem_base) {
    const char* aH = (const char*)g_Xh + (size_t)(mt * 16 + kc) * A_TILE;
    const char* bH = (const char*)g_Wh + (size_t)(nt * 16 + kc) * B_TILE;
    const uint32_t sAh = smem_base + s * STAGE_BYTES;
    const uint32_t sBh = sAh + A_TILE;
    const uint32_t to = (uint32_t)tid * 16;
    #pragma unroll
    for (int i = 0; i < 4; ++i) {
        const uint32_t o = (uint32_t)i * 4096 + to;
        cp_async16(sAh + o, aH + o);
        cp_async16(sBh + o, bH + o);
    }
}

__global__ void __launch_bounds__(256, 2) gemm_k(const float* __restrict__ bias,
                                                 float* __restrict__ out) {
    extern __shared__ __align__(1024) char smem[];
    const uint32_t smem_base = smem_u32(smem);
    const int tid = threadIdx.x;
    const int l   = tid & 31;
    const int wid = tid >> 5;
    const int wm  = wid & 3;     // m 32-block (0..3)
    const int wn  = wid >> 2;    // n 64-block (0..1)
    const int bx  = blockIdx.x;
    const int nt  = bx & 7;
    const int mt  = bx >> 3;

    // per-lane ldmatrix address components
    uint32_t a_off[2], a_ph[2];
    #pragma unroll
    for (int mb = 0; mb < 2; ++mb) {
        const int row = wm * 32 + mb * 16 + (l & 15);
        a_off[mb] = (uint32_t)row * 128;
        a_ph[mb]  = (uint32_t)(row & 7) * 16;
    }
    const uint32_t a_half = (uint32_t)(l >> 4) * 16;
    const int bmat = l >> 3;
    uint32_t b_off[4], b_ph[4];
    #pragma unroll
    for (int nb2 = 0; nb2 < 4; ++nb2) {
        const int row = wn * 64 + nb2 * 16 + (bmat >> 1) * 8 + (l & 7);
        b_off[nb2] = (uint32_t)row * 128;
        b_ph[nb2]  = (uint32_t)(row & 7) * 16;
    }
    const uint32_t b_half = (uint32_t)(bmat & 1) * 16;

    float acc[2][8][4];
    #pragma unroll
    for (int mb = 0; mb < 2; ++mb)
        #pragma unroll
        for (int nb = 0; nb < 8; ++nb)
            #pragma unroll
            for (int i = 0; i < 4; ++i) acc[mb][nb][i] = 0.f;

    uint32_t ah[2][4], bf[8][2];

    // fragment loader (single rotating buffer)
    auto load_frags = [&](uint32_t stage_base, uint32_t kbyte) {
        const uint32_t sAh = stage_base;
        const uint32_t sBh = stage_base + A_TILE;
        #pragma unroll
        for (int mb = 0; mb < 2; ++mb)
            ldsm_x4(ah[mb], sAh + a_off[mb] + ((kbyte + a_half) ^ a_ph[mb]));
        #pragma unroll
        for (int nb2 = 0; nb2 < 4; ++nb2) {
            uint32_t r[4];
            ldsm_x4(r, sBh + b_off[nb2] + ((kbyte + b_half) ^ b_ph[nb2]));
            bf[nb2 * 2][0]     = r[0]; bf[nb2 * 2][1]     = r[1];
            bf[nb2 * 2 + 1][0] = r[2]; bf[nb2 * 2 + 1][1] = r[3];
        }
    };

    // prologue: stages 0,1 in flight; frags kk0 of stage 0 in regs
    issue_loads(0, 0, mt, nt, tid, smem_base); CP_COMMIT();
    issue_loads(1, 1, mt, nt, tid, smem_base); CP_COMMIT();
    CP_WAIT1();
    __syncthreads();
    load_frags(smem_base, 0);

    for (int it = 0; it < KCHUNKS; ++it) {
        const uint32_t scb = smem_base + (it % 3) * STAGE_BYTES;

        #pragma unroll
        for (int kk = 0; kk < 4; ++kk) {
            #pragma unroll
            for (int mb = 0; mb < 2; ++mb)
                #pragma unroll
                for (int nb = 0; nb < 8; ++nb)
                    mma16816(acc[mb][nb], ah[mb], bf[nb][0], bf[nb][1]);
            if (kk < 3) load_frags(scb, (uint32_t)(kk + 1) * 32);
        }

        if (it + 1 < KCHUNKS) {
            CP_WAIT0();          // G(it+1) issued a full iteration ago: already landed
            __syncthreads();     // all threads' copies visible; stage (it+2)%3 free
            load_frags(smem_base + ((it + 1) % 3) * STAGE_BYTES, 0);  // next iter kk0
            if (it + 2 < KCHUNKS) {
                issue_loads(it + 2, (it + 2) % 3, mt, nt, tid, smem_base);
                CP_COMMIT();
            }
        }
    }
    __syncthreads();   // protect smem reuse by epilogue

    // ---------------- epilogue: transposed sCT, conflict-free, 512B stores ----------------
    float* sCT = (float*)smem;           // [128 cols][PT=132 rows]
    const int bg = mt / 108;
    const int b  = bg >> 1;
    const int g  = bg & 1;
    const int sp0 = (mt % 108) * 128;
    float* outB = out + (size_t)b * C_ * XSTR + sp0;

    #pragma unroll
    for (int mb = 0; mb < 2; ++mb) {
        const int row = wm * 32 + mb * 16 + (l >> 2);
        #pragma unroll
        for (int nb = 0; nb < 8; ++nb) {
            const int cc = wn * 64 + nb * 8 + (l & 3) * 2;
            sCT[cc * PT + row]           = acc[mb][nb][0];
            sCT[(cc + 1) * PT + row]     = acc[mb][nb][1];
            sCT[cc * PT + row + 8]       = acc[mb][nb][2];
            sCT[(cc + 1) * PT + row + 8] = acc[mb][nb][3];
        }
    }
    __syncthreads();

    #pragma unroll
    for (int j = 0; j < 16; ++j) {
        const int col = wid * 16 + j;
        const int o   = nt * 128 + col;
        const int sv  = o >> 5;
        const int c   = o & 31;
        const int tp  = (g * 32 + sv + 48) & 63;
        const float bia = __ldg(&bias[o]);
        float4 v = *(float4*)&sCT[col * PT + 4 * l];
        v.x += bia; v.y += bia; v.z += bia; v.w += bia;
        float* dst = outB + (size_t)c * XSTR + (size_t)tp * SP + 4 * l;
        *(float4*)dst = v;
    }
}

// ---------------- host ----------------
extern "C" void kernel_launch(void* const* d_in, const int* in_sizes, int n_in,
                              void* d_out, int out_size) {
    const float* x    = (const float*)d_in[0];
    const float* W    = (const float*)d_in[1];
    const float* bias = (const float*)d_in[2];
    float* out = (float*)d_out;

    cudaFuncSetAttribute(gemm_k, cudaFuncAttributeMaxDynamicSharedMemorySize, SMEM_DYN);

    prepass_x<<<MTILES * KCHUNKS, 128>>>(x);                 // 6912 blocks
    prepass_w<<<NTILES * KCHUNKS, 128>>>(W);                 // 128 blocks
    gemm_k<<<MTILES * NTILES, 256, SMEM_DYN>>>(bias, out);   // 3456 blocks
}